// round 6
// baseline (speedup 1.0000x reference)
#include <cuda_runtime.h>
#include <cuda_bf16.h>
#include <cstdint>

// Problem constants (fixed shapes per reference)
#define NNODES 50000
#define MAXE   800000
#define DF     128
#define SLOT   96        // per-node CSR bucket capacity (Poisson(16) max ~42)

// ---------------- device scratch (no allocations allowed) ----------------
__device__ int g_fmt;                  // 1 => edge_index int64, 0 => int32
__device__ int g_deg[NNODES];          // doubles as fill cursor
__device__ int g_csr[(size_t)NNODES * SLOT];

__device__ __nv_bfloat16 g_xb[(size_t)NNODES * DF];
__device__ __nv_bfloat16 g_meanb[(size_t)NNODES * DF];   // also reused as uv buffer
__device__ __nv_bfloat16 g_hAb[(size_t)NNODES * DF];
__device__ __nv_bfloat16 g_hBb[(size_t)NNODES * DF];
// bf16 weights, contiguous: W1l, W1r, W2l, W2r (16384 each), W3l, W3r (8192)
__device__ __nv_bfloat16 g_wb[4 * 16384 + 2 * 8192];

// ---------------- fp32 -> bf16 conversion (x) ----------------
__global__ void k_cvt(const float* __restrict__ src, __nv_bfloat16* __restrict__ dst, int n4) {
    int i = blockIdx.x * blockDim.x + threadIdx.x;
    if (i >= n4) return;
    float4 v = reinterpret_cast<const float4*>(src)[i];
    __nv_bfloat162 lo = __floats2bfloat162_rn(v.x, v.y);
    __nv_bfloat162 hi = __floats2bfloat162_rn(v.z, v.w);
    uint2 o;
    o.x = *reinterpret_cast<unsigned int*>(&lo);
    o.y = *reinterpret_cast<unsigned int*>(&hi);
    reinterpret_cast<uint2*>(dst)[i] = o;
}

// ---------------- all 6 weight matrices -> bf16, one kernel ----------------
__global__ void k_cvtw(const float* __restrict__ W1l, const float* __restrict__ W1r,
                       const float* __restrict__ W2l, const float* __restrict__ W2r,
                       const float* __restrict__ W3l, const float* __restrict__ W3r) {
    int i = blockIdx.x * blockDim.x + threadIdx.x;     // float4 unit, 20480 total
    if (i >= 20480) return;
    const float* src;
    int li;
    if      (i < 4096)  { src = W1l; li = i; }
    else if (i < 8192)  { src = W1r; li = i - 4096; }
    else if (i < 12288) { src = W2l; li = i - 8192; }
    else if (i < 16384) { src = W2r; li = i - 12288; }
    else if (i < 18432) { src = W3l; li = i - 16384; }
    else                { src = W3r; li = i - 18432; }
    float4 v = reinterpret_cast<const float4*>(src)[li];
    __nv_bfloat162 lo = __floats2bfloat162_rn(v.x, v.y);
    __nv_bfloat162 hi = __floats2bfloat162_rn(v.z, v.w);
    uint2 o;
    o.x = *reinterpret_cast<unsigned int*>(&lo);
    o.y = *reinterpret_cast<unsigned int*>(&hi);
    reinterpret_cast<uint2*>(g_wb)[i] = o;
}

// ---------------- init: edge dtype detect + zero degree counters ----------
__global__ void k_init(const unsigned int* __restrict__ w) {
    int gid = blockIdx.x * blockDim.x + threadIdx.x;
    int stride = gridDim.x * blockDim.x;
    for (int i = gid; i < NNODES; i += stride) g_deg[i] = 0;
    if (blockIdx.x == 0) {
        __shared__ int flag;
        if (threadIdx.x == 0) flag = 0;
        __syncthreads();
        for (int i = threadIdx.x; i < 1024; i += blockDim.x)
            if (w[2 * i + 1] != 0u) flag = 1;      // benign race
        __syncthreads();
        if (threadIdx.x == 0) g_fmt = flag ? 0 : 1;
    }
}

// ---------------- single-pass bucketed CSR fill (2 edges/thread) ----------
// E is even for this problem (800000) so 16B/8B vector loads stay aligned.
__global__ void k_fill(const void* __restrict__ eptr, int E) {
    int t = blockIdx.x * blockDim.x + threadIdx.x;
    int e = t * 2;
    if (e >= E) return;
    int s0, d0, s1, d1;
    if (g_fmt) {
        const long long* p = (const long long*)eptr;
        longlong2 sv = *reinterpret_cast<const longlong2*>(p + e);
        longlong2 dv = *reinterpret_cast<const longlong2*>(p + E + e);
        s0 = (int)sv.x; s1 = (int)sv.y;
        d0 = (int)dv.x; d1 = (int)dv.y;
    } else {
        const int* p = (const int*)eptr;
        int2 sv = *reinterpret_cast<const int2*>(p + e);
        int2 dv = *reinterpret_cast<const int2*>(p + E + e);
        s0 = sv.x; s1 = sv.y;
        d0 = dv.x; d1 = dv.y;
    }
    int p0 = atomicAdd(&g_deg[d0], 1);
    if (p0 < SLOT) g_csr[(size_t)d0 * SLOT + p0] = s0;
    if (e + 1 < E) {
        int p1 = atomicAdd(&g_deg[d1], 1);
        if (p1 < SLOT) g_csr[(size_t)d1 * SLOT + p1] = s1;
    }
}

// ---------------- mean aggregation (bf16 gather, fp32 accum, bf16 out) -----
__global__ void k_agg(const __nv_bfloat16* __restrict__ hin, __nv_bfloat16* __restrict__ meanout) {
    int warp = threadIdx.x >> 5;
    int lane = threadIdx.x & 31;
    int node = blockIdx.x * 8 + warp;
    if (node >= NNODES) return;
    int deg = g_deg[node];
    if (deg > SLOT) deg = SLOT;
    const int* row = g_csr + (size_t)node * SLOT;
    float4 acc = make_float4(0.f, 0.f, 0.f, 0.f);
#define ACC4(u) { \
        float2 f0 = __bfloat1622float2(*reinterpret_cast<__nv_bfloat162*>(&u.x)); \
        float2 f1 = __bfloat1622float2(*reinterpret_cast<__nv_bfloat162*>(&u.y)); \
        acc.x += f0.x; acc.y += f0.y; acc.z += f1.x; acc.w += f1.y; }
    int i = 0;
    for (; i + 8 <= deg; i += 8) {
        uint2 u[8];
#pragma unroll
        for (int j = 0; j < 8; j++) {
            int s = __ldg(&row[i + j]);
            u[j] = *reinterpret_cast<const uint2*>(hin + (size_t)s * DF + lane * 4);
        }
#pragma unroll
        for (int j = 0; j < 8; j++) ACC4(u[j])
    }
    for (; i < deg; i++) {
        int s = __ldg(&row[i]);
        uint2 u = *reinterpret_cast<const uint2*>(hin + (size_t)s * DF + lane * 4);
        ACC4(u)
    }
#undef ACC4
    float inv = (deg > 0) ? 1.f / (float)deg : 0.f;
    __nv_bfloat162 lo = __floats2bfloat162_rn(acc.x * inv, acc.y * inv);
    __nv_bfloat162 hi = __floats2bfloat162_rn(acc.z * inv, acc.w * inv);
    uint2 o;
    o.x = *reinterpret_cast<unsigned int*>(&lo);
    o.y = *reinterpret_cast<unsigned int*>(&hi);
    *reinterpret_cast<uint2*>(meanout + (size_t)node * DF + lane * 4) = o;
}

// ---------------- layer-3 finish: mean(u) + v -> sigmoid -> global sum -----
// uv[node] = [ u(64) | v(64) ] bf16.  out[64] += sigmoid(mean_u + v).
__global__ void k_agg3(const __nv_bfloat16* __restrict__ uv, float* __restrict__ out) {
    __shared__ float so[64];
    int tid = threadIdx.x;
    int warp = tid >> 5, lane = tid & 31;
    if (tid < 64) so[tid] = 0.f;
    __syncthreads();
    int node = blockIdx.x * 8 + warp;
    float t0 = 0.f, t1 = 0.f;
    if (node < NNODES) {
        int deg = g_deg[node];
        if (deg > SLOT) deg = SLOT;
        const int* row = g_csr + (size_t)node * SLOT;
        float a0 = 0.f, a1 = 0.f;
        int i = 0;
        for (; i + 8 <= deg; i += 8) {
            unsigned int u[8];
#pragma unroll
            for (int j = 0; j < 8; j++) {
                int s = __ldg(&row[i + j]);
                u[j] = *reinterpret_cast<const unsigned int*>(uv + (size_t)s * 128 + lane * 2);
            }
#pragma unroll
            for (int j = 0; j < 8; j++) {
                float2 f = __bfloat1622float2(*reinterpret_cast<__nv_bfloat162*>(&u[j]));
                a0 += f.x; a1 += f.y;
            }
        }
        for (; i < deg; i++) {
            int s = __ldg(&row[i]);
            unsigned int u = *reinterpret_cast<const unsigned int*>(uv + (size_t)s * 128 + lane * 2);
            float2 f = __bfloat1622float2(*reinterpret_cast<__nv_bfloat162*>(&u));
            a0 += f.x; a1 += f.y;
        }
        float inv = (deg > 0) ? 1.f / (float)deg : 0.f;
        unsigned int vb = *reinterpret_cast<const unsigned int*>(uv + (size_t)node * 128 + 64 + lane * 2);
        float2 fv = __bfloat1622float2(*reinterpret_cast<__nv_bfloat162*>(&vb));
        t0 = 1.f / (1.f + __expf(-(a0 * inv + fv.x)));
        t1 = 1.f / (1.f + __expf(-(a1 * inv + fv.y)));
    }
    atomicAdd(&so[lane * 2], t0);
    atomicAdd(&so[lane * 2 + 1], t1);
    __syncthreads();
    if (tid < 64) atomicAdd(&out[tid], so[tid]);
}

// ---------------- tensor-core GEMM (mma.sync m16n8k16 bf16) ---------------
// UV=false (layers 1,2): A=[mean||h] (128xKD=256), W=[Wl;Wr] per col,
//   out = sigmoid(A·Wᵀ + b) bf16, DOUT=128.
// UV=true (layer 3):  A=h (128x128), cols 0..63 = W3l rows (u, bias 0),
//   cols 64..127 = W3r rows (v, bias b3), no activation, out bf16.
template <int KD, bool UV>
__global__ void __launch_bounds__(256)
k_gemm(const __nv_bfloat16* __restrict__ meanin, const __nv_bfloat16* __restrict__ hin,
       const __nv_bfloat16* __restrict__ Wlb, const float* __restrict__ bias,
       const __nv_bfloat16* __restrict__ Wrb, __nv_bfloat16* __restrict__ out) {
    constexpr int DOUT = 128;
    constexpr int BM = 128;
    constexpr int SA = 264;
    constexpr int SW = 264;
    constexpr int KC = KD / 8;      // uint4 chunks per row

    extern __shared__ __align__(16) char smraw[];
    __nv_bfloat16* Ws = reinterpret_cast<__nv_bfloat16*>(smraw);   // DOUT*SW
    __nv_bfloat16* As = Ws + DOUT * SW;                            // BM*SA
    float* bs = reinterpret_cast<float*>(As + BM * SA);            // DOUT

    int tid  = threadIdx.x;
    int row0 = blockIdx.x * BM;

    // stage weights
    for (int i = tid; i < DOUT * KC; i += 256) {
        int n = i / KC, c = i % KC;
        if (!UV) {
            // KC == 32: c<16 from Wl row n, c>=16 from Wr row n
            uint4 v = (c < 16) ? reinterpret_cast<const uint4*>(Wlb)[n * 16 + c]
                               : reinterpret_cast<const uint4*>(Wrb)[n * 16 + (c - 16)];
            *reinterpret_cast<uint4*>(&Ws[n * SW + c * 8]) = v;
        } else {
            // KC == 16: n<64 from W3l row n, n>=64 from W3r row n-64
            uint4 v = (n < 64) ? reinterpret_cast<const uint4*>(Wlb)[n * 16 + c]
                               : reinterpret_cast<const uint4*>(Wrb)[(n - 64) * 16 + c];
            *reinterpret_cast<uint4*>(&Ws[n * SW + c * 8]) = v;
        }
    }
    if (tid < DOUT) {
        if (!UV) bs[tid] = bias[tid];
        else     bs[tid] = (tid < 64) ? 0.f : bias[tid - 64];
    }

    // stage inputs
    for (int i = tid; i < BM * KC; i += 256) {
        int r = i / KC, c = i % KC;
        int row = row0 + r;
        uint4 v = make_uint4(0, 0, 0, 0);
        if (row < NNODES) {
            if (!UV) v = (c < 16) ? reinterpret_cast<const uint4*>(meanin)[row * 16 + c]
                                  : reinterpret_cast<const uint4*>(hin)[row * 16 + (c - 16)];
            else     v = reinterpret_cast<const uint4*>(hin)[row * 16 + c];
        }
        *reinterpret_cast<uint4*>(&As[r * SA + c * 8]) = v;
    }
    __syncthreads();

    int lane = tid & 31, wid = tid >> 5;
    int gid  = lane >> 2, tg = lane & 3;
    int wm = wid >> 1, wn = wid & 1;
    int rowb  = wm * 32;
    int ncolb = wn * 64;

    float c[2][8][4];
#pragma unroll
    for (int mt = 0; mt < 2; mt++)
#pragma unroll
        for (int nt = 0; nt < 8; nt++)
#pragma unroll
            for (int q = 0; q < 4; q++) c[mt][nt][q] = 0.f;

#pragma unroll
    for (int kk = 0; kk < KD / 16; kk++) {
        unsigned int bf[8][2];
#pragma unroll
        for (int nt = 0; nt < 8; nt++) {
            const __nv_bfloat16* bp = &Ws[(ncolb + nt * 8 + gid) * SW + kk * 16 + tg * 2];
            bf[nt][0] = *reinterpret_cast<const unsigned int*>(bp);
            bf[nt][1] = *reinterpret_cast<const unsigned int*>(bp + 8);
        }
#pragma unroll
        for (int mt = 0; mt < 2; mt++) {
            int r = rowb + mt * 16 + gid;
            const __nv_bfloat16* ap0 = &As[r * SA + kk * 16 + tg * 2];
            const __nv_bfloat16* ap1 = &As[(r + 8) * SA + kk * 16 + tg * 2];
            unsigned int a0 = *reinterpret_cast<const unsigned int*>(ap0);
            unsigned int a1 = *reinterpret_cast<const unsigned int*>(ap1);
            unsigned int a2 = *reinterpret_cast<const unsigned int*>(ap0 + 8);
            unsigned int a3 = *reinterpret_cast<const unsigned int*>(ap1 + 8);
#pragma unroll
            for (int nt = 0; nt < 8; nt++) {
                asm volatile(
                    "mma.sync.aligned.m16n8k16.row.col.f32.bf16.bf16.f32 "
                    "{%0,%1,%2,%3}, {%4,%5,%6,%7}, {%8,%9}, {%0,%1,%2,%3};"
                    : "+f"(c[mt][nt][0]), "+f"(c[mt][nt][1]),
                      "+f"(c[mt][nt][2]), "+f"(c[mt][nt][3])
                    : "r"(a0), "r"(a1), "r"(a2), "r"(a3),
                      "r"(bf[nt][0]), "r"(bf[nt][1]));
            }
        }
    }

#pragma unroll
    for (int mt = 0; mt < 2; mt++) {
        int ro = row0 + rowb + mt * 16 + gid;
#pragma unroll
        for (int nt = 0; nt < 8; nt++) {
            int col = ncolb + nt * 8 + tg * 2;
            float b0 = bs[col], b1 = bs[col + 1];
            if (ro < NNODES) {
                float v0 = c[mt][nt][0] + b0;
                float v1 = c[mt][nt][1] + b1;
                if (!UV) { v0 = 1.f / (1.f + __expf(-v0)); v1 = 1.f / (1.f + __expf(-v1)); }
                __nv_bfloat162 pv = __floats2bfloat162_rn(v0, v1);
                *reinterpret_cast<__nv_bfloat162*>(&out[(size_t)ro * DOUT + col]) = pv;
            }
            if (ro + 8 < NNODES) {
                float v2 = c[mt][nt][2] + b0;
                float v3 = c[mt][nt][3] + b1;
                if (!UV) { v2 = 1.f / (1.f + __expf(-v2)); v3 = 1.f / (1.f + __expf(-v3)); }
                __nv_bfloat162 pv = __floats2bfloat162_rn(v2, v3);
                *reinterpret_cast<__nv_bfloat162*>(&out[(size_t)(ro + 8) * DOUT + col]) = pv;
            }
        }
    }
}

// ---------------- launch ----------------
extern "C" void kernel_launch(void* const* d_in, const int* in_sizes, int n_in,
                              void* d_out, int out_size) {
    const float* x    = (const float*)d_in[0];
    const void*  eidx = d_in[1];
    const float* W1l  = (const float*)d_in[2];
    const float* b1   = (const float*)d_in[3];
    const float* W1r  = (const float*)d_in[4];
    const float* W2l  = (const float*)d_in[5];
    const float* b2   = (const float*)d_in[6];
    const float* W2r  = (const float*)d_in[7];
    const float* W3l  = (const float*)d_in[8];
    const float* b3   = (const float*)d_in[9];
    const float* W3r  = (const float*)d_in[10];

    int E = in_sizes[1] / 2;
    if (E > MAXE) E = MAXE;

    void *pXB, *pMB, *pAB, *pBB, *pWB;
    cudaGetSymbolAddress(&pXB, g_xb);
    cudaGetSymbolAddress(&pMB, g_meanb);
    cudaGetSymbolAddress(&pAB, g_hAb);
    cudaGetSymbolAddress(&pBB, g_hBb);
    cudaGetSymbolAddress(&pWB, g_wb);
    __nv_bfloat16* xb    = (__nv_bfloat16*)pXB;
    __nv_bfloat16* meanb = (__nv_bfloat16*)pMB;
    __nv_bfloat16* hAb   = (__nv_bfloat16*)pAB;
    __nv_bfloat16* hBb   = (__nv_bfloat16*)pBB;
    __nv_bfloat16* wb    = (__nv_bfloat16*)pWB;
    __nv_bfloat16* w1l = wb;
    __nv_bfloat16* w1r = wb + 16384;
    __nv_bfloat16* w2l = wb + 2 * 16384;
    __nv_bfloat16* w2r = wb + 3 * 16384;
    __nv_bfloat16* w3l = wb + 4 * 16384;
    __nv_bfloat16* w3r = wb + 4 * 16384 + 8192;

    const int smem = (128 * 264 + 128 * 264) * 2 + 128 * 4;
    cudaFuncSetAttribute(k_gemm<256, false>, cudaFuncAttributeMaxDynamicSharedMemorySize, smem);
    cudaFuncSetAttribute(k_gemm<128, true>,  cudaFuncAttributeMaxDynamicSharedMemorySize, smem);

    int fgrid = (E / 2 + 255) / 256;
    int agrid = (NNODES + 7) / 8;
    int ggrid = (NNODES + 127) / 128;
    int xn4   = NNODES * DF / 4;

    // order chosen so launch #4 (ncu -s 3 -c 1 capture) is k_agg layer 1
    k_cvt<<<(xn4 + 255) / 256, 256>>>(x, xb, xn4);                  // 1
    k_init<<<196, 256>>>((const unsigned int*)eidx);                // 2
    k_fill<<<fgrid, 256>>>(eidx, E);                                // 3
    k_agg<<<agrid, 256>>>(xb, meanb);                               // 4  <- profiled
    k_cvtw<<<80, 256>>>(W1l, W1r, W2l, W2r, W3l, W3r);              // 5

    // layer 1
    k_gemm<256, false><<<ggrid, 256, smem>>>(meanb, xb, w1l, b1, w1r, hAb);
    // layer 2
    k_agg<<<agrid, 256>>>(hAb, meanb);
    k_gemm<256, false><<<ggrid, 256, smem>>>(meanb, hAb, w2l, b2, w2r, hBb);
    // layer 3: transform first (u|v), then aggregate + sigmoid + global sum
    k_gemm<128, true><<<ggrid, 256, smem>>>(nullptr, hBb, w3l, b3, w3r, meanb);
    cudaMemsetAsync(d_out, 0, 64 * sizeof(float), 0);
    k_agg3<<<agrid, 256>>>(meanb, (float*)d_out);
}

// round 7
// speedup vs baseline: 1.1428x; 1.1428x over previous
#include <cuda_runtime.h>
#include <cuda_bf16.h>
#include <cstdint>

// Problem constants (fixed shapes per reference)
#define NNODES 50000
#define MAXE   800000
#define DF     128
#define SLOT   96        // per-node CSR bucket capacity (Poisson(16) max ~42)

// ---------------- device scratch (no allocations allowed) ----------------
__device__ int g_fmt;                  // 1 => edge_index int64, 0 => int32
__device__ int g_deg[NNODES];          // doubles as fill cursor
__device__ __align__(16) int g_csr[(size_t)NNODES * SLOT];

__device__ __align__(16) __nv_bfloat16 g_xb[(size_t)NNODES * DF];
__device__ __align__(16) __nv_bfloat16 g_meanb[(size_t)NNODES * DF];
__device__ __align__(16) __nv_bfloat16 g_hAb[(size_t)NNODES * DF];
__device__ __align__(16) __nv_bfloat16 g_hBb[(size_t)NNODES * DF];
// bf16 weights, contiguous: W1l, W1r, W2l, W2r (16384 each), W3l, W3r (8192)
__device__ __align__(16) __nv_bfloat16 g_wb[4 * 16384 + 2 * 8192];

// ---------------- fp32 -> bf16 conversion (x) ----------------
__global__ void k_cvt(const float* __restrict__ src, __nv_bfloat16* __restrict__ dst, int n4) {
    int i = blockIdx.x * blockDim.x + threadIdx.x;
    if (i >= n4) return;
    float4 v = reinterpret_cast<const float4*>(src)[i];
    __nv_bfloat162 lo = __floats2bfloat162_rn(v.x, v.y);
    __nv_bfloat162 hi = __floats2bfloat162_rn(v.z, v.w);
    uint2 o;
    o.x = *reinterpret_cast<unsigned int*>(&lo);
    o.y = *reinterpret_cast<unsigned int*>(&hi);
    reinterpret_cast<uint2*>(dst)[i] = o;
}

// ---------------- all 6 weight matrices -> bf16, one kernel ----------------
__global__ void k_cvtw(const float* __restrict__ W1l, const float* __restrict__ W1r,
                       const float* __restrict__ W2l, const float* __restrict__ W2r,
                       const float* __restrict__ W3l, const float* __restrict__ W3r) {
    int i = blockIdx.x * blockDim.x + threadIdx.x;     // float4 unit, 20480 total
    if (i >= 20480) return;
    const float* src;
    int li;
    if      (i < 4096)  { src = W1l; li = i; }
    else if (i < 8192)  { src = W1r; li = i - 4096; }
    else if (i < 12288) { src = W2l; li = i - 8192; }
    else if (i < 16384) { src = W2r; li = i - 12288; }
    else if (i < 18432) { src = W3l; li = i - 16384; }
    else                { src = W3r; li = i - 18432; }
    float4 v = reinterpret_cast<const float4*>(src)[li];
    __nv_bfloat162 lo = __floats2bfloat162_rn(v.x, v.y);
    __nv_bfloat162 hi = __floats2bfloat162_rn(v.z, v.w);
    uint2 o;
    o.x = *reinterpret_cast<unsigned int*>(&lo);
    o.y = *reinterpret_cast<unsigned int*>(&hi);
    reinterpret_cast<uint2*>(g_wb)[i] = o;
}

// ---------------- init: edge dtype detect + zero degree counters ----------
__global__ void k_init(const unsigned int* __restrict__ w) {
    int gid = blockIdx.x * blockDim.x + threadIdx.x;
    int stride = gridDim.x * blockDim.x;
    for (int i = gid; i < NNODES; i += stride) g_deg[i] = 0;
    if (blockIdx.x == 0) {
        __shared__ int flag;
        if (threadIdx.x == 0) flag = 0;
        __syncthreads();
        for (int i = threadIdx.x; i < 1024; i += blockDim.x)
            if (w[2 * i + 1] != 0u) flag = 1;      // benign race
        __syncthreads();
        if (threadIdx.x == 0) g_fmt = flag ? 0 : 1;
    }
}

// ---------------- single-pass bucketed CSR fill (2 edges/thread) ----------
__global__ void k_fill(const void* __restrict__ eptr, int E) {
    int t = blockIdx.x * blockDim.x + threadIdx.x;
    int e = t * 2;
    if (e >= E) return;
    int s0, d0, s1, d1;
    if (g_fmt) {
        const long long* p = (const long long*)eptr;
        longlong2 sv = *reinterpret_cast<const longlong2*>(p + e);
        longlong2 dv = *reinterpret_cast<const longlong2*>(p + E + e);
        s0 = (int)sv.x; s1 = (int)sv.y;
        d0 = (int)dv.x; d1 = (int)dv.y;
    } else {
        const int* p = (const int*)eptr;
        int2 sv = *reinterpret_cast<const int2*>(p + e);
        int2 dv = *reinterpret_cast<const int2*>(p + E + e);
        s0 = sv.x; s1 = sv.y;
        d0 = dv.x; d1 = dv.y;
    }
    int p0 = atomicAdd(&g_deg[d0], 1);
    if (p0 < SLOT) g_csr[(size_t)d0 * SLOT + p0] = s0;
    if (e + 1 < E) {
        int p1 = atomicAdd(&g_deg[d1], 1);
        if (p1 < SLOT) g_csr[(size_t)d1 * SLOT + p1] = s1;
    }
}

// ---------------- mean aggregation, issue-optimized ------------------------
// One warp per node, 2 edges per step: lanes 0-15 take edge i, lanes 16-31
// edge i+1; each lane gathers an 8-dim uint4 (LDG.128). bf16->f32 expansion
// via exact SHL/AND (bf16 == top half of f32), accumulate with packed
// add.rn.f32x2. Parity partials combined by shfl_xor(16) at the end.
__global__ void k_agg(const __nv_bfloat16* __restrict__ hin, __nv_bfloat16* __restrict__ meanout) {
    int warp = threadIdx.x >> 5;
    int lane = threadIdx.x & 31;
    int node = blockIdx.x * 8 + warp;
    if (node >= NNODES) return;
    int deg = g_deg[node];
    if (deg > SLOT) deg = SLOT;
    const int* row = g_csr + (size_t)node * SLOT;
    int g   = lane >> 4;        // which edge of the pair
    int sub = lane & 15;        // 8-dim chunk
    const __nv_bfloat16* base = hin + sub * 8;

    unsigned long long a0 = 0ull, a1 = 0ull, a2 = 0ull, a3 = 0ull;  // {0.f,0.f} bits

#define ACC2(accv, v) { \
    unsigned int _lo = (v) << 16; \
    unsigned int _hi = (v) & 0xFFFF0000u; \
    unsigned long long _p; \
    asm("mov.b64 %0, {%1,%2};" : "=l"(_p) : "r"(_lo), "r"(_hi)); \
    asm("add.rn.f32x2 %0, %0, %1;" : "+l"(accv) : "l"(_p)); }
#define ACCU4(u) { ACC2(a0, (u).x) ACC2(a1, (u).y) ACC2(a2, (u).z) ACC2(a3, (u).w) }

    int dmain = deg & ~1;
    int i = 0;
    for (; i + 4 <= dmain; i += 4) {
        int4 s4 = *reinterpret_cast<const int4*>(row + i);      // uniform LDG.128
        int sA = g ? s4.y : s4.x;
        int sB = g ? s4.w : s4.z;
        uint4 uA = *reinterpret_cast<const uint4*>(base + (size_t)sA * DF);
        uint4 uB = *reinterpret_cast<const uint4*>(base + (size_t)sB * DF);
        ACCU4(uA)
        ACCU4(uB)
    }
    for (; i < dmain; i += 2) {
        int2 s2 = *reinterpret_cast<const int2*>(row + i);
        int s = g ? s2.y : s2.x;
        uint4 u = *reinterpret_cast<const uint4*>(base + (size_t)s * DF);
        ACCU4(u)
    }
    if ((deg & 1) && g == 0) {                                   // odd tail: group 0 only
        int s = __ldg(&row[deg - 1]);
        uint4 u = *reinterpret_cast<const uint4*>(base + (size_t)s * DF);
        ACCU4(u)
    }
#undef ACCU4
#undef ACC2

    // combine edge-parity halves (lane <-> lane^16)
    unsigned long long o0 = __shfl_xor_sync(0xFFFFFFFFu, a0, 16);
    unsigned long long o1 = __shfl_xor_sync(0xFFFFFFFFu, a1, 16);
    unsigned long long o2 = __shfl_xor_sync(0xFFFFFFFFu, a2, 16);
    unsigned long long o3 = __shfl_xor_sync(0xFFFFFFFFu, a3, 16);
    asm("add.rn.f32x2 %0, %0, %1;" : "+l"(a0) : "l"(o0));
    asm("add.rn.f32x2 %0, %0, %1;" : "+l"(a1) : "l"(o1));
    asm("add.rn.f32x2 %0, %0, %1;" : "+l"(a2) : "l"(o2));
    asm("add.rn.f32x2 %0, %0, %1;" : "+l"(a3) : "l"(o3));

    if (g == 0) {
        float inv = (deg > 0) ? 1.f / (float)deg : 0.f;
        float f[8];
        asm("mov.b64 {%0,%1}, %2;" : "=f"(f[0]), "=f"(f[1]) : "l"(a0));
        asm("mov.b64 {%0,%1}, %2;" : "=f"(f[2]), "=f"(f[3]) : "l"(a1));
        asm("mov.b64 {%0,%1}, %2;" : "=f"(f[4]), "=f"(f[5]) : "l"(a2));
        asm("mov.b64 {%0,%1}, %2;" : "=f"(f[6]), "=f"(f[7]) : "l"(a3));
        __nv_bfloat162 b0 = __floats2bfloat162_rn(f[0] * inv, f[1] * inv);
        __nv_bfloat162 b1 = __floats2bfloat162_rn(f[2] * inv, f[3] * inv);
        __nv_bfloat162 b2 = __floats2bfloat162_rn(f[4] * inv, f[5] * inv);
        __nv_bfloat162 b3 = __floats2bfloat162_rn(f[6] * inv, f[7] * inv);
        uint4 o;
        o.x = *reinterpret_cast<unsigned int*>(&b0);
        o.y = *reinterpret_cast<unsigned int*>(&b1);
        o.z = *reinterpret_cast<unsigned int*>(&b2);
        o.w = *reinterpret_cast<unsigned int*>(&b3);
        *reinterpret_cast<uint4*>(meanout + (size_t)node * DF + sub * 8) = o;
    }
}

// ---------------- tensor-core GEMM + bias + sigmoid (+ final reduce) -------
// out[row][col] = sigmoid( mean[row]·Wl[col] + h[row]·Wr[col] + b[col] )
// A = [mean || h] (BM=128 x K=256 bf16), B = [Wl ; Wr] as Ws[n][k] row-major.
// mma.sync.m16n8k16 bf16; fragment loads are conflict-free LDS.32.
template <int DOUT, bool LAST>
__global__ void __launch_bounds__(256)
k_gemm(const __nv_bfloat16* __restrict__ meanin, const __nv_bfloat16* __restrict__ hin,
       const __nv_bfloat16* __restrict__ Wlb, const float* __restrict__ bias,
       const __nv_bfloat16* __restrict__ Wrb, void* __restrict__ outp) {
    constexpr int BM = 128;
    constexpr int SA = 264;
    constexpr int SW = 264;
    constexpr int WN = (DOUT == 128) ? 2 : 1;
    constexpr int MT = (DOUT == 128) ? 2 : 1;

    extern __shared__ __align__(16) char smraw[];
    __nv_bfloat16* Ws = reinterpret_cast<__nv_bfloat16*>(smraw);   // DOUT*SW
    __nv_bfloat16* As = Ws + DOUT * SW;                            // BM*SA
    float* bs = reinterpret_cast<float*>(As + BM * SA);            // DOUT
    __shared__ float so[64];

    int tid  = threadIdx.x;
    int row0 = blockIdx.x * BM;
    if (LAST && tid < 64) so[tid] = 0.f;

    for (int i = tid; i < DOUT * 16; i += 256) {
        int n = i >> 4, c = i & 15;
        uint4 vl = reinterpret_cast<const uint4*>(Wlb)[n * 16 + c];
        uint4 vr = reinterpret_cast<const uint4*>(Wrb)[n * 16 + c];
        *reinterpret_cast<uint4*>(&Ws[n * SW + c * 8])       = vl;
        *reinterpret_cast<uint4*>(&Ws[n * SW + 128 + c * 8]) = vr;
    }
    if (tid < DOUT) bs[tid] = bias[tid];

    for (int i = tid; i < BM * 16; i += 256) {
        int r = i >> 4, c = i & 15;
        int row = row0 + r;
        uint4 vm = make_uint4(0, 0, 0, 0), vh = make_uint4(0, 0, 0, 0);
        if (row < NNODES) {
            vm = reinterpret_cast<const uint4*>(meanin)[row * 16 + c];
            vh = reinterpret_cast<const uint4*>(hin)[row * 16 + c];
        }
        *reinterpret_cast<uint4*>(&As[r * SA + c * 8])       = vm;
        *reinterpret_cast<uint4*>(&As[r * SA + 128 + c * 8]) = vh;
    }
    __syncthreads();

    int lane = tid & 31, wid = tid >> 5;
    int gid  = lane >> 2, tg = lane & 3;
    int wm = wid / WN, wn = wid % WN;
    int rowb  = wm * (MT * 16);
    int ncolb = wn * 64;

    float c[MT][8][4];
#pragma unroll
    for (int mt = 0; mt < MT; mt++)
#pragma unroll
        for (int nt = 0; nt < 8; nt++)
#pragma unroll
            for (int q = 0; q < 4; q++) c[mt][nt][q] = 0.f;

#pragma unroll
    for (int kk = 0; kk < 16; kk++) {
        unsigned int bf[8][2];
#pragma unroll
        for (int nt = 0; nt < 8; nt++) {
            const __nv_bfloat16* bp = &Ws[(ncolb + nt * 8 + gid) * SW + kk * 16 + tg * 2];
            bf[nt][0] = *reinterpret_cast<const unsigned int*>(bp);
            bf[nt][1] = *reinterpret_cast<const unsigned int*>(bp + 8);
        }
#pragma unroll
        for (int mt = 0; mt < MT; mt++) {
            int r = rowb + mt * 16 + gid;
            const __nv_bfloat16* ap0 = &As[r * SA + kk * 16 + tg * 2];
            const __nv_bfloat16* ap1 = &As[(r + 8) * SA + kk * 16 + tg * 2];
            unsigned int a0 = *reinterpret_cast<const unsigned int*>(ap0);
            unsigned int a1 = *reinterpret_cast<const unsigned int*>(ap1);
            unsigned int a2 = *reinterpret_cast<const unsigned int*>(ap0 + 8);
            unsigned int a3 = *reinterpret_cast<const unsigned int*>(ap1 + 8);
#pragma unroll
            for (int nt = 0; nt < 8; nt++) {
                asm volatile(
                    "mma.sync.aligned.m16n8k16.row.col.f32.bf16.bf16.f32 "
                    "{%0,%1,%2,%3}, {%4,%5,%6,%7}, {%8,%9}, {%0,%1,%2,%3};"
                    : "+f"(c[mt][nt][0]), "+f"(c[mt][nt][1]),
                      "+f"(c[mt][nt][2]), "+f"(c[mt][nt][3])
                    : "r"(a0), "r"(a1), "r"(a2), "r"(a3),
                      "r"(bf[nt][0]), "r"(bf[nt][1]));
            }
        }
    }

    if (!LAST) {
        __nv_bfloat16* out = reinterpret_cast<__nv_bfloat16*>(outp);
#pragma unroll
        for (int mt = 0; mt < MT; mt++) {
            int ro = row0 + rowb + mt * 16 + gid;
#pragma unroll
            for (int nt = 0; nt < 8; nt++) {
                int col = ncolb + nt * 8 + tg * 2;
                float b0 = bs[col], b1 = bs[col + 1];
                if (ro < NNODES) {
                    float v0 = 1.f / (1.f + __expf(-(c[mt][nt][0] + b0)));
                    float v1 = 1.f / (1.f + __expf(-(c[mt][nt][1] + b1)));
                    __nv_bfloat162 pv = __floats2bfloat162_rn(v0, v1);
                    *reinterpret_cast<__nv_bfloat162*>(&out[(size_t)ro * DOUT + col]) = pv;
                }
                if (ro + 8 < NNODES) {
                    float v2 = 1.f / (1.f + __expf(-(c[mt][nt][2] + b0)));
                    float v3 = 1.f / (1.f + __expf(-(c[mt][nt][3] + b1)));
                    __nv_bfloat162 pv = __floats2bfloat162_rn(v2, v3);
                    *reinterpret_cast<__nv_bfloat162*>(&out[(size_t)(ro + 8) * DOUT + col]) = pv;
                }
            }
        }
    } else {
        float* out = reinterpret_cast<float*>(outp);
        int ro = row0 + rowb + gid;
#pragma unroll
        for (int nt = 0; nt < 8; nt++) {
            int col = nt * 8 + tg * 2;
            float b0 = bs[col], b1 = bs[col + 1];
            float t0 = 0.f, t1 = 0.f;
            if (ro < NNODES) {
                t0 += 1.f / (1.f + __expf(-(c[0][nt][0] + b0)));
                t1 += 1.f / (1.f + __expf(-(c[0][nt][1] + b1)));
            }
            if (ro + 8 < NNODES) {
                t0 += 1.f / (1.f + __expf(-(c[0][nt][2] + b0)));
                t1 += 1.f / (1.f + __expf(-(c[0][nt][3] + b1)));
            }
#pragma unroll
            for (int o = 4; o < 32; o <<= 1) {
                t0 += __shfl_xor_sync(0xFFFFFFFFu, t0, o);
                t1 += __shfl_xor_sync(0xFFFFFFFFu, t1, o);
            }
            if (lane < 4) {
                atomicAdd(&so[col], t0);
                atomicAdd(&so[col + 1], t1);
            }
        }
        __syncthreads();
        if (tid < 64) atomicAdd(&out[tid], so[tid]);
    }
}

// ---------------- launch ----------------
extern "C" void kernel_launch(void* const* d_in, const int* in_sizes, int n_in,
                              void* d_out, int out_size) {
    const float* x    = (const float*)d_in[0];
    const void*  eidx = d_in[1];
    const float* W1l  = (const float*)d_in[2];
    const float* b1   = (const float*)d_in[3];
    const float* W1r  = (const float*)d_in[4];
    const float* W2l  = (const float*)d_in[5];
    const float* b2   = (const float*)d_in[6];
    const float* W2r  = (const float*)d_in[7];
    const float* W3l  = (const float*)d_in[8];
    const float* b3   = (const float*)d_in[9];
    const float* W3r  = (const float*)d_in[10];

    int E = in_sizes[1] / 2;
    if (E > MAXE) E = MAXE;

    void *pXB, *pMB, *pAB, *pBB, *pWB;
    cudaGetSymbolAddress(&pXB, g_xb);
    cudaGetSymbolAddress(&pMB, g_meanb);
    cudaGetSymbolAddress(&pAB, g_hAb);
    cudaGetSymbolAddress(&pBB, g_hBb);
    cudaGetSymbolAddress(&pWB, g_wb);
    __nv_bfloat16* xb    = (__nv_bfloat16*)pXB;
    __nv_bfloat16* meanb = (__nv_bfloat16*)pMB;
    __nv_bfloat16* hAb   = (__nv_bfloat16*)pAB;
    __nv_bfloat16* hBb   = (__nv_bfloat16*)pBB;
    __nv_bfloat16* wb    = (__nv_bfloat16*)pWB;
    __nv_bfloat16* w1l = wb;
    __nv_bfloat16* w1r = wb + 16384;
    __nv_bfloat16* w2l = wb + 2 * 16384;
    __nv_bfloat16* w2r = wb + 3 * 16384;
    __nv_bfloat16* w3l = wb + 4 * 16384;
    __nv_bfloat16* w3r = wb + 4 * 16384 + 8192;

    const int smem12 = (128 * 264 + 128 * 264) * 2 + 128 * 4;
    const int smem3  = (64 * 264 + 128 * 264) * 2 + 64 * 4;
    cudaFuncSetAttribute(k_gemm<128, false>, cudaFuncAttributeMaxDynamicSharedMemorySize, smem12);
    cudaFuncSetAttribute(k_gemm<64,  true>,  cudaFuncAttributeMaxDynamicSharedMemorySize, smem3);

    int fgrid = (E / 2 + 255) / 256;
    int agrid = (NNODES + 7) / 8;
    int ggrid = (NNODES + 127) / 128;
    int xn4   = NNODES * DF / 4;

    // order chosen so launch #4 (ncu capture) is k_agg layer 1
    k_cvt<<<(xn4 + 255) / 256, 256>>>(x, xb, xn4);                  // 1
    k_init<<<196, 256>>>((const unsigned int*)eidx);                // 2
    k_fill<<<fgrid, 256>>>(eidx, E);                                // 3
    k_agg<<<agrid, 256>>>(xb, meanb);                               // 4  <- profiled
    k_cvtw<<<80, 256>>>(W1l, W1r, W2l, W2r, W3l, W3r);              // 5

    // layer 1
    k_gemm<128, false><<<ggrid, 256, smem12>>>(meanb, xb, w1l, b1, w1r, hAb);
    // layer 2
    k_agg<<<agrid, 256>>>(hAb, meanb);
    k_gemm<128, false><<<ggrid, 256, smem12>>>(meanb, hAb, w2l, b2, w2r, hBb);
    // layer 3 + fused global sum
    k_agg<<<agrid, 256>>>(hBb, meanb);
    cudaMemsetAsync(d_out, 0, 64 * sizeof(float), 0);
    k_gemm<64, true><<<ggrid, 256, smem3>>>(meanb, hBb, w3l, b3, w3r, d_out);
}

// round 8
// speedup vs baseline: 1.2168x; 1.0647x over previous
#include <cuda_runtime.h>
#include <cuda_bf16.h>
#include <cstdint>

// Problem constants (fixed shapes per reference)
#define NNODES 50000
#define MAXE   800000
#define DF     128
#define SLOT   96        // per-node CSR bucket capacity (Poisson(16) max ~42)

// ---------------- device scratch (no allocations allowed) ----------------
__device__ int g_fmt;                  // 1 => edge_index int64, 0 => int32
__device__ int g_deg[NNODES];          // doubles as fill cursor
__device__ __align__(16) int g_csr[(size_t)NNODES * SLOT];

__device__ __align__(16) __nv_bfloat16 g_xb[(size_t)NNODES * DF];
__device__ __align__(16) __nv_bfloat16 g_meanb[(size_t)NNODES * DF];
__device__ __align__(16) __nv_bfloat16 g_hAb[(size_t)NNODES * DF];
__device__ __align__(16) __nv_bfloat16 g_hBb[(size_t)NNODES * DF];
// bf16 weights, contiguous: W1l, W1r, W2l, W2r (16384 each), W3l, W3r (8192)
__device__ __align__(16) __nv_bfloat16 g_wb[4 * 16384 + 2 * 8192];

// ---------------- one-shot prep: conversions + init + out zero ------------
// gid < 400000: convert x (float4 -> bf16x4)
// gid < 20480:  convert the 6 weight matrices into g_wb
// gid < NNODES: zero degree counters
// gid < 64:     zero d_out
// block 0:      edge dtype detection
__global__ void k_prep(const float* __restrict__ x,
                       const unsigned int* __restrict__ ew,
                       const float* __restrict__ W1l, const float* __restrict__ W1r,
                       const float* __restrict__ W2l, const float* __restrict__ W2r,
                       const float* __restrict__ W3l, const float* __restrict__ W3r,
                       float* __restrict__ out) {
    int gid = blockIdx.x * blockDim.x + threadIdx.x;
    const int XN4 = NNODES * DF / 4;            // 1.6M floats -> 400000 float4

    if (gid < XN4) {
        float4 v = reinterpret_cast<const float4*>(x)[gid];
        __nv_bfloat162 lo = __floats2bfloat162_rn(v.x, v.y);
        __nv_bfloat162 hi = __floats2bfloat162_rn(v.z, v.w);
        uint2 o;
        o.x = *reinterpret_cast<unsigned int*>(&lo);
        o.y = *reinterpret_cast<unsigned int*>(&hi);
        reinterpret_cast<uint2*>(g_xb)[gid] = o;
    }
    if (gid < 20480) {
        const float* src;
        int li;
        if      (gid < 4096)  { src = W1l; li = gid; }
        else if (gid < 8192)  { src = W1r; li = gid - 4096; }
        else if (gid < 12288) { src = W2l; li = gid - 8192; }
        else if (gid < 16384) { src = W2r; li = gid - 12288; }
        else if (gid < 18432) { src = W3l; li = gid - 16384; }
        else                  { src = W3r; li = gid - 18432; }
        float4 v = reinterpret_cast<const float4*>(src)[li];
        __nv_bfloat162 lo = __floats2bfloat162_rn(v.x, v.y);
        __nv_bfloat162 hi = __floats2bfloat162_rn(v.z, v.w);
        uint2 o;
        o.x = *reinterpret_cast<unsigned int*>(&lo);
        o.y = *reinterpret_cast<unsigned int*>(&hi);
        reinterpret_cast<uint2*>(g_wb)[gid] = o;
    }
    if (gid < NNODES) g_deg[gid] = 0;
    if (gid < 64)     out[gid] = 0.f;
    if (blockIdx.x == 0) {
        __shared__ int flag;
        if (threadIdx.x == 0) flag = 0;
        __syncthreads();
        for (int i = threadIdx.x; i < 1024; i += blockDim.x)
            if (ew[2 * i + 1] != 0u) flag = 1;   // benign race
        __syncthreads();
        if (threadIdx.x == 0) g_fmt = flag ? 0 : 1;
    }
}

// ---------------- single-pass bucketed CSR fill (2 edges/thread) ----------
__global__ void k_fill(const void* __restrict__ eptr, int E) {
    int t = blockIdx.x * blockDim.x + threadIdx.x;
    int e = t * 2;
    if (e >= E) return;
    int s0, d0, s1, d1;
    if (g_fmt) {
        const long long* p = (const long long*)eptr;
        longlong2 sv = *reinterpret_cast<const longlong2*>(p + e);
        longlong2 dv = *reinterpret_cast<const longlong2*>(p + E + e);
        s0 = (int)sv.x; s1 = (int)sv.y;
        d0 = (int)dv.x; d1 = (int)dv.y;
    } else {
        const int* p = (const int*)eptr;
        int2 sv = *reinterpret_cast<const int2*>(p + e);
        int2 dv = *reinterpret_cast<const int2*>(p + E + e);
        s0 = sv.x; s1 = sv.y;
        d0 = dv.x; d1 = dv.y;
    }
    int p0 = atomicAdd(&g_deg[d0], 1);
    if (p0 < SLOT) g_csr[(size_t)d0 * SLOT + p0] = s0;
    if (e + 1 < E) {
        int p1 = atomicAdd(&g_deg[d1], 1);
        if (p1 < SLOT) g_csr[(size_t)d1 * SLOT + p1] = s1;
    }
}

// ---------------- mean aggregation (R5 form + int4 index loads) ------------
__global__ void k_agg(const __nv_bfloat16* __restrict__ hin, __nv_bfloat16* __restrict__ meanout) {
    int warp = threadIdx.x >> 5;
    int lane = threadIdx.x & 31;
    int node = blockIdx.x * 8 + warp;
    if (node >= NNODES) return;
    int deg = g_deg[node];
    if (deg > SLOT) deg = SLOT;
    const int* row = g_csr + (size_t)node * SLOT;
    const __nv_bfloat16* base = hin + lane * 4;
    float4 acc = make_float4(0.f, 0.f, 0.f, 0.f);
#define ACC4(u) { \
        float2 f0 = __bfloat1622float2(*reinterpret_cast<__nv_bfloat162*>(&u.x)); \
        float2 f1 = __bfloat1622float2(*reinterpret_cast<__nv_bfloat162*>(&u.y)); \
        acc.x += f0.x; acc.y += f0.y; acc.z += f1.x; acc.w += f1.y; }
    int i = 0;
    for (; i + 8 <= deg; i += 8) {
        int4 sa = *reinterpret_cast<const int4*>(row + i);
        int4 sb = *reinterpret_cast<const int4*>(row + i + 4);
        uint2 u[8];
        u[0] = *reinterpret_cast<const uint2*>(base + (size_t)sa.x * DF);
        u[1] = *reinterpret_cast<const uint2*>(base + (size_t)sa.y * DF);
        u[2] = *reinterpret_cast<const uint2*>(base + (size_t)sa.z * DF);
        u[3] = *reinterpret_cast<const uint2*>(base + (size_t)sa.w * DF);
        u[4] = *reinterpret_cast<const uint2*>(base + (size_t)sb.x * DF);
        u[5] = *reinterpret_cast<const uint2*>(base + (size_t)sb.y * DF);
        u[6] = *reinterpret_cast<const uint2*>(base + (size_t)sb.z * DF);
        u[7] = *reinterpret_cast<const uint2*>(base + (size_t)sb.w * DF);
#pragma unroll
        for (int j = 0; j < 8; j++) ACC4(u[j])
    }
    for (; i < deg; i++) {
        int s = __ldg(&row[i]);
        uint2 u = *reinterpret_cast<const uint2*>(base + (size_t)s * DF);
        ACC4(u)
    }
#undef ACC4
    float inv = (deg > 0) ? 1.f / (float)deg : 0.f;
    __nv_bfloat162 lo = __floats2bfloat162_rn(acc.x * inv, acc.y * inv);
    __nv_bfloat162 hi = __floats2bfloat162_rn(acc.z * inv, acc.w * inv);
    uint2 o;
    o.x = *reinterpret_cast<unsigned int*>(&lo);
    o.y = *reinterpret_cast<unsigned int*>(&hi);
    *reinterpret_cast<uint2*>(meanout + (size_t)node * DF + lane * 4) = o;
}

// ---------------- tensor-core GEMM + bias + sigmoid (+ final reduce) -------
// out[row][col] = sigmoid( mean[row]·Wl[col] + h[row]·Wr[col] + b[col] )
// A = [mean || h] (BM=128 x K=256 bf16), B = [Wl ; Wr] as Ws[n][k] row-major.
// mma.sync.m16n8k16 bf16; fragment loads are conflict-free LDS.32.
template <int DOUT, bool LAST>
__global__ void __launch_bounds__(256)
k_gemm(const __nv_bfloat16* __restrict__ meanin, const __nv_bfloat16* __restrict__ hin,
       const __nv_bfloat16* __restrict__ Wlb, const float* __restrict__ bias,
       const __nv_bfloat16* __restrict__ Wrb, void* __restrict__ outp) {
    constexpr int BM = 128;
    constexpr int SA = 264;
    constexpr int SW = 264;
    constexpr int WN = (DOUT == 128) ? 2 : 1;
    constexpr int MT = (DOUT == 128) ? 2 : 1;

    extern __shared__ __align__(16) char smraw[];
    __nv_bfloat16* Ws = reinterpret_cast<__nv_bfloat16*>(smraw);   // DOUT*SW
    __nv_bfloat16* As = Ws + DOUT * SW;                            // BM*SA
    float* bs = reinterpret_cast<float*>(As + BM * SA);            // DOUT
    __shared__ float so[64];

    int tid  = threadIdx.x;
    int row0 = blockIdx.x * BM;
    if (LAST && tid < 64) so[tid] = 0.f;

    for (int i = tid; i < DOUT * 16; i += 256) {
        int n = i >> 4, c = i & 15;
        uint4 vl = reinterpret_cast<const uint4*>(Wlb)[n * 16 + c];
        uint4 vr = reinterpret_cast<const uint4*>(Wrb)[n * 16 + c];
        *reinterpret_cast<uint4*>(&Ws[n * SW + c * 8])       = vl;
        *reinterpret_cast<uint4*>(&Ws[n * SW + 128 + c * 8]) = vr;
    }
    if (tid < DOUT) bs[tid] = bias[tid];

    for (int i = tid; i < BM * 16; i += 256) {
        int r = i >> 4, c = i & 15;
        int row = row0 + r;
        uint4 vm = make_uint4(0, 0, 0, 0), vh = make_uint4(0, 0, 0, 0);
        if (row < NNODES) {
            vm = reinterpret_cast<const uint4*>(meanin)[row * 16 + c];
            vh = reinterpret_cast<const uint4*>(hin)[row * 16 + c];
        }
        *reinterpret_cast<uint4*>(&As[r * SA + c * 8])       = vm;
        *reinterpret_cast<uint4*>(&As[r * SA + 128 + c * 8]) = vh;
    }
    __syncthreads();

    int lane = tid & 31, wid = tid >> 5;
    int gid  = lane >> 2, tg = lane & 3;
    int wm = wid / WN, wn = wid % WN;
    int rowb  = wm * (MT * 16);
    int ncolb = wn * 64;

    float c[MT][8][4];
#pragma unroll
    for (int mt = 0; mt < MT; mt++)
#pragma unroll
        for (int nt = 0; nt < 8; nt++)
#pragma unroll
            for (int q = 0; q < 4; q++) c[mt][nt][q] = 0.f;

#pragma unroll
    for (int kk = 0; kk < 16; kk++) {
        unsigned int bf[8][2];
#pragma unroll
        for (int nt = 0; nt < 8; nt++) {
            const __nv_bfloat16* bp = &Ws[(ncolb + nt * 8 + gid) * SW + kk * 16 + tg * 2];
            bf[nt][0] = *reinterpret_cast<const unsigned int*>(bp);
            bf[nt][1] = *reinterpret_cast<const unsigned int*>(bp + 8);
        }
#pragma unroll
        for (int mt = 0; mt < MT; mt++) {
            int r = rowb + mt * 16 + gid;
            const __nv_bfloat16* ap0 = &As[r * SA + kk * 16 + tg * 2];
            const __nv_bfloat16* ap1 = &As[(r + 8) * SA + kk * 16 + tg * 2];
            unsigned int a0 = *reinterpret_cast<const unsigned int*>(ap0);
            unsigned int a1 = *reinterpret_cast<const unsigned int*>(ap1);
            unsigned int a2 = *reinterpret_cast<const unsigned int*>(ap0 + 8);
            unsigned int a3 = *reinterpret_cast<const unsigned int*>(ap1 + 8);
#pragma unroll
            for (int nt = 0; nt < 8; nt++) {
                asm volatile(
                    "mma.sync.aligned.m16n8k16.row.col.f32.bf16.bf16.f32 "
                    "{%0,%1,%2,%3}, {%4,%5,%6,%7}, {%8,%9}, {%0,%1,%2,%3};"
                    : "+f"(c[mt][nt][0]), "+f"(c[mt][nt][1]),
                      "+f"(c[mt][nt][2]), "+f"(c[mt][nt][3])
                    : "r"(a0), "r"(a1), "r"(a2), "r"(a3),
                      "r"(bf[nt][0]), "r"(bf[nt][1]));
            }
        }
    }

    if (!LAST) {
        __nv_bfloat16* out = reinterpret_cast<__nv_bfloat16*>(outp);
#pragma unroll
        for (int mt = 0; mt < MT; mt++) {
            int ro = row0 + rowb + mt * 16 + gid;
#pragma unroll
            for (int nt = 0; nt < 8; nt++) {
                int col = ncolb + nt * 8 + tg * 2;
                float b0 = bs[col], b1 = bs[col + 1];
                if (ro < NNODES) {
                    float v0 = 1.f / (1.f + __expf(-(c[mt][nt][0] + b0)));
                    float v1 = 1.f / (1.f + __expf(-(c[mt][nt][1] + b1)));
                    __nv_bfloat162 pv = __floats2bfloat162_rn(v0, v1);
                    *reinterpret_cast<__nv_bfloat162*>(&out[(size_t)ro * DOUT + col]) = pv;
                }
                if (ro + 8 < NNODES) {
                    float v2 = 1.f / (1.f + __expf(-(c[mt][nt][2] + b0)));
                    float v3 = 1.f / (1.f + __expf(-(c[mt][nt][3] + b1)));
                    __nv_bfloat162 pv = __floats2bfloat162_rn(v2, v3);
                    *reinterpret_cast<__nv_bfloat162*>(&out[(size_t)(ro + 8) * DOUT + col]) = pv;
                }
            }
        }
    } else {
        float* out = reinterpret_cast<float*>(outp);
        int ro = row0 + rowb + gid;
#pragma unroll
        for (int nt = 0; nt < 8; nt++) {
            int col = nt * 8 + tg * 2;
            float b0 = bs[col], b1 = bs[col + 1];
            float t0 = 0.f, t1 = 0.f;
            if (ro < NNODES) {
                t0 += 1.f / (1.f + __expf(-(c[0][nt][0] + b0)));
                t1 += 1.f / (1.f + __expf(-(c[0][nt][1] + b1)));
            }
            if (ro + 8 < NNODES) {
                t0 += 1.f / (1.f + __expf(-(c[0][nt][2] + b0)));
                t1 += 1.f / (1.f + __expf(-(c[0][nt][3] + b1)));
            }
#pragma unroll
            for (int o = 4; o < 32; o <<= 1) {
                t0 += __shfl_xor_sync(0xFFFFFFFFu, t0, o);
                t1 += __shfl_xor_sync(0xFFFFFFFFu, t1, o);
            }
            if (lane < 4) {
                atomicAdd(&so[col], t0);
                atomicAdd(&so[col + 1], t1);
            }
        }
        __syncthreads();
        if (tid < 64) atomicAdd(&out[tid], so[tid]);
    }
}

// ---------------- launch ----------------
extern "C" void kernel_launch(void* const* d_in, const int* in_sizes, int n_in,
                              void* d_out, int out_size) {
    const float* x    = (const float*)d_in[0];
    const void*  eidx = d_in[1];
    const float* W1l  = (const float*)d_in[2];
    const float* b1   = (const float*)d_in[3];
    const float* W1r  = (const float*)d_in[4];
    const float* W2l  = (const float*)d_in[5];
    const float* b2   = (const float*)d_in[6];
    const float* W2r  = (const float*)d_in[7];
    const float* W3l  = (const float*)d_in[8];
    const float* b3   = (const float*)d_in[9];
    const float* W3r  = (const float*)d_in[10];

    int E = in_sizes[1] / 2;
    if (E > MAXE) E = MAXE;

    void *pXB, *pMB, *pAB, *pBB, *pWB;
    cudaGetSymbolAddress(&pXB, g_xb);
    cudaGetSymbolAddress(&pMB, g_meanb);
    cudaGetSymbolAddress(&pAB, g_hAb);
    cudaGetSymbolAddress(&pBB, g_hBb);
    cudaGetSymbolAddress(&pWB, g_wb);
    __nv_bfloat16* xb    = (__nv_bfloat16*)pXB;
    __nv_bfloat16* meanb = (__nv_bfloat16*)pMB;
    __nv_bfloat16* hAb   = (__nv_bfloat16*)pAB;
    __nv_bfloat16* hBb   = (__nv_bfloat16*)pBB;
    __nv_bfloat16* wb    = (__nv_bfloat16*)pWB;
    __nv_bfloat16* w1l = wb;
    __nv_bfloat16* w1r = wb + 16384;
    __nv_bfloat16* w2l = wb + 2 * 16384;
    __nv_bfloat16* w2r = wb + 3 * 16384;
    __nv_bfloat16* w3l = wb + 4 * 16384;
    __nv_bfloat16* w3r = wb + 4 * 16384 + 8192;

    const int smem12 = (128 * 264 + 128 * 264) * 2 + 128 * 4;
    const int smem3  = (64 * 264 + 128 * 264) * 2 + 64 * 4;
    cudaFuncSetAttribute(k_gemm<128, false>, cudaFuncAttributeMaxDynamicSharedMemorySize, smem12);
    cudaFuncSetAttribute(k_gemm<64,  true>,  cudaFuncAttributeMaxDynamicSharedMemorySize, smem3);

    int fgrid = (E / 2 + 255) / 256;
    int agrid = (NNODES + 7) / 8;
    int ggrid = (NNODES + 127) / 128;
    int pgrid = (NNODES * DF / 4 + 255) / 256;   // covers all prep jobs

    // order: prep(1), fill(2), agg(3), gemm(4) <- ncu capture on gemm layer 1
    k_prep<<<pgrid, 256>>>(x, (const unsigned int*)eidx,
                           W1l, W1r, W2l, W2r, W3l, W3r, (float*)d_out);
    k_fill<<<fgrid, 256>>>(eidx, E);
    // layer 1
    k_agg<<<agrid, 256>>>(xb, meanb);
    k_gemm<128, false><<<ggrid, 256, smem12>>>(meanb, xb, w1l, b1, w1r, hAb);
    // layer 2
    k_agg<<<agrid, 256>>>(hAb, meanb);
    k_gemm<128, false><<<ggrid, 256, smem12>>>(meanb, hAb, w2l, b2, w2r, hBb);
    // layer 3 + fused global sum
    k_agg<<<agrid, 256>>>(hBb, meanb);
    k_gemm<64, true><<<ggrid, 256, smem3>>>(meanb, hBb, w3l, b3, w3r, d_out);
}